// round 3
// baseline (speedup 1.0000x reference)
#include <cuda_runtime.h>

// Problem constants (match reference)
#define B_ROWS   65536
#define N_SPARSE 26
#define VOCAB    5000
#define N_DENSE  13

#define ROWS_PER_BLOCK 128   // one thread per row
#define IDX_STRIDE     27    // pad 26 -> 27 (odd) for conflict-free smem reads

// Thread-per-row design:
//  - Block stages sparse_idx [128x26] and dense [128x13] into smem with fully
//    coalesced global loads.
//  - Each thread then owns one row: 26 embedding gathers (L2-hot, issued as an
//    unrolled batch -> MLP ~26), 2 cross-table DRAM gathers, 13 dense FMAs.
//  - No shuffles, no cross-lane reduction, all 32 lanes do identical full work.

__global__ __launch_bounds__(ROWS_PER_BLOCK) void wide_kernel(
    const float* __restrict__ dense,        // [B, 13]
    const float* __restrict__ emb_table,    // [26, 5000]
    const float* __restrict__ cross_table0, // [25e6]
    const float* __restrict__ cross_table1, // [25e6]
    const float* __restrict__ dense_w,      // [13]
    const int*   __restrict__ sparse_idx,   // [B, 26] int32
    float*       __restrict__ out)          // [B]
{
    __shared__ int   s_idx[ROWS_PER_BLOCK * IDX_STRIDE];
    __shared__ float s_dense[ROWS_PER_BLOCK * N_DENSE];
    __shared__ float s_w[N_DENSE];

    const int tid  = threadIdx.x;
    const int row0 = blockIdx.x * ROWS_PER_BLOCK;

    if (tid < N_DENSE) s_w[tid] = __ldg(&dense_w[tid]);

    // Stage sparse_idx tile: 128*26 = 3328 ints, coalesced, re-laid to stride 27.
    #pragma unroll
    for (int j = tid; j < ROWS_PER_BLOCK * N_SPARSE; j += ROWS_PER_BLOCK) {
        int v = __ldg(&sparse_idx[row0 * N_SPARSE + j]);
        int r = j / N_SPARSE;
        int c = j - r * N_SPARSE;
        s_idx[r * IDX_STRIDE + c] = v;
    }

    // Stage dense tile: 128*13 = 1664 floats, coalesced, natural stride 13 (odd).
    #pragma unroll
    for (int j = tid; j < ROWS_PER_BLOCK * N_DENSE; j += ROWS_PER_BLOCK) {
        s_dense[j] = __ldg(&dense[row0 * N_DENSE + j]);
    }

    __syncthreads();

    const int* my = &s_idx[tid * IDX_STRIDE];

    // Embedding gathers: 26 independent L2-hot loads, batched by unroll.
    float acc = 0.0f;
    #pragma unroll
    for (int f = 0; f < N_SPARSE; f++) {
        acc += __ldg(&emb_table[f * VOCAB + my[f]]);
    }

    // Cross features: 2 independent random DRAM gathers (max 24,999,999 < INT_MAX).
    acc += __ldg(&cross_table0[my[0] * VOCAB + my[1]]);
    acc += __ldg(&cross_table1[my[2] * VOCAB + my[3]]);

    // Dense dot from smem (stride 13: conflict-free).
    const float* dr = &s_dense[tid * N_DENSE];
    #pragma unroll
    for (int d = 0; d < N_DENSE; d++) {
        acc += dr[d] * s_w[d];
    }

    out[row0 + tid] = acc;
}

extern "C" void kernel_launch(void* const* d_in, const int* in_sizes, int n_in,
                              void* d_out, int out_size)
{
    // Defensive pointer identification by element count (cross tables keep order).
    const float* dense        = nullptr;
    const float* emb_table    = nullptr;
    const float* cross_table0 = nullptr;
    const float* cross_table1 = nullptr;
    const float* dense_w      = nullptr;
    const int*   sparse_idx   = nullptr;

    for (int i = 0; i < n_in; i++) {
        const long long sz = in_sizes[i];
        if      (sz == (long long)B_ROWS * N_DENSE)   dense      = (const float*)d_in[i];
        else if (sz == (long long)N_SPARSE * VOCAB)   emb_table  = (const float*)d_in[i];
        else if (sz == (long long)VOCAB * VOCAB) {
            if (!cross_table0) cross_table0 = (const float*)d_in[i];
            else               cross_table1 = (const float*)d_in[i];
        }
        else if (sz == N_DENSE)                       dense_w    = (const float*)d_in[i];
        else if (sz == (long long)B_ROWS * N_SPARSE)  sparse_idx = (const int*)d_in[i];
    }

    float* out = (float*)d_out;

    const int blocks = B_ROWS / ROWS_PER_BLOCK;   // 512
    wide_kernel<<<blocks, ROWS_PER_BLOCK>>>(dense, emb_table, cross_table0, cross_table1,
                                            dense_w, sparse_idx, out);
}

// round 4
// speedup vs baseline: 1.2745x; 1.2745x over previous
#include <cuda_runtime.h>

// Problem constants
#define B_ROWS   65536
#define N_SPARSE 26
#define VOCAB    5000
#define N_DENSE  13

#define NBLOCKS     148
#define THREADS     512
#define ROWS_PB     443           // ceil(65536/148); last block has 415
#define IDX_STRIDE  27            // pad 26 -> 27, coprime with 32 banks

// Feature split: features [0,17) gathered from smem table slices (3 passes),
// features [17,26) + 2 cross tables gathered directly through L1/L2/DRAM.
#define N_CACHED    17
#define N_DIRECT    (N_SPARSE - N_CACHED)   // 9
#define PASS_MAX    6                       // max features per smem pass

// Dynamic smem layout (bytes):
//   [0, TABLE_BYTES)            : table slice, up to 6*5000 floats = 120000 B
//   [TABLE_BYTES, +IDX_BYTES)   : staged idx, 443*27 ints = 47844 B
//   [.., +DENSE_BYTES)          : staged dense, 443*13 floats = 23036 B
#define TABLE_BYTES (PASS_MAX * VOCAB * 4)
#define IDX_BYTES   (ROWS_PB * IDX_STRIDE * 4)
#define DENSE_BYTES (ROWS_PB * N_DENSE * 4)
#define SMEM_TOTAL  (TABLE_BYTES + IDX_BYTES + DENSE_BYTES)   // 190880 B

__global__ __launch_bounds__(THREADS, 1) void wide_kernel(
    const float* __restrict__ dense,        // [B, 13]
    const float* __restrict__ emb_table,    // [26, 5000]
    const float* __restrict__ cross_table0, // [25e6]
    const float* __restrict__ cross_table1, // [25e6]
    const float* __restrict__ dense_w,      // [13]
    const int*   __restrict__ sparse_idx,   // [B, 26] int32
    float*       __restrict__ out)          // [B]
{
    extern __shared__ char smem[];
    float* s_table = (float*)smem;
    int*   s_idx   = (int*)(smem + TABLE_BYTES);
    float* s_dense = (float*)(smem + TABLE_BYTES + IDX_BYTES);

    const int tid  = threadIdx.x;
    const int row0 = blockIdx.x * ROWS_PB;
    const int rows = min(ROWS_PB, B_ROWS - row0);

    // ---- Stage sparse_idx (coalesced -> stride-27 smem) ----
    const int nidx = rows * N_SPARSE;
    for (int j = tid; j < nidx; j += THREADS) {
        int v = __ldg(&sparse_idx[row0 * N_SPARSE + j]);
        int r = j / N_SPARSE;
        int c = j - r * N_SPARSE;
        s_idx[r * IDX_STRIDE + c] = v;
    }
    // ---- Stage dense (coalesced, natural stride-13) ----
    const int nden = rows * N_DENSE;
    for (int j = tid; j < nden; j += THREADS) {
        s_dense[j] = __ldg(&dense[row0 * N_DENSE + j]);
    }
    __syncthreads();

    const bool active = (tid < rows);
    const int* my = &s_idx[tid * IDX_STRIDE];

    float acc = 0.0f;
    if (active) {
        // Direct gathers: 9 tail features + 2 cross tables. Issued early so
        // their latency overlaps the first table-slice copy below.
        #pragma unroll
        for (int f = N_CACHED; f < N_SPARSE; f++) {
            acc += __ldg(&emb_table[f * VOCAB + my[f]]);
        }
        acc += __ldg(&cross_table0[my[0] * VOCAB + my[1]]);
        acc += __ldg(&cross_table1[my[2] * VOCAB + my[3]]);

        // Dense dot: s_dense stride-13 (coprime 32 -> conflict-free);
        // dense_w is warp-uniform -> broadcast loads.
        const float* dr = &s_dense[tid * N_DENSE];
        #pragma unroll
        for (int d = 0; d < N_DENSE; d++) {
            acc += dr[d] * __ldg(&dense_w[d]);
        }
    }

    // ---- Cached feature passes: {6, 6, 5} over features [0, 17) ----
    #pragma unroll
    for (int p = 0; p < 3; p++) {
        const int f0 = p * PASS_MAX;
        const int nf = (p == 2) ? (N_CACHED - 2 * PASS_MAX) : PASS_MAX;   // 6,6,5

        // Cooperative copy of contiguous table region [f0*VOCAB, (f0+nf)*VOCAB)
        const float4* src = (const float4*)(emb_table + f0 * VOCAB);
        float4*       dst = (float4*)s_table;
        const int nvec = nf * VOCAB / 4;   // 5000*4 % 16 == 0, 16B-aligned
        for (int j = tid; j < nvec; j += THREADS) {
            dst[j] = __ldg(&src[j]);
        }
        __syncthreads();

        if (active) {
            #pragma unroll
            for (int f = 0; f < PASS_MAX; f++) {
                if (f < nf) acc += s_table[f * VOCAB + my[f0 + f]];
            }
        }
        __syncthreads();
    }

    if (active) out[row0 + tid] = acc;
}

extern "C" void kernel_launch(void* const* d_in, const int* in_sizes, int n_in,
                              void* d_out, int out_size)
{
    const float* dense        = nullptr;
    const float* emb_table    = nullptr;
    const float* cross_table0 = nullptr;
    const float* cross_table1 = nullptr;
    const float* dense_w      = nullptr;
    const int*   sparse_idx   = nullptr;

    for (int i = 0; i < n_in; i++) {
        const long long sz = in_sizes[i];
        if      (sz == (long long)B_ROWS * N_DENSE)   dense      = (const float*)d_in[i];
        else if (sz == (long long)N_SPARSE * VOCAB)   emb_table  = (const float*)d_in[i];
        else if (sz == (long long)VOCAB * VOCAB) {
            if (!cross_table0) cross_table0 = (const float*)d_in[i];
            else               cross_table1 = (const float*)d_in[i];
        }
        else if (sz == N_DENSE)                       dense_w    = (const float*)d_in[i];
        else if (sz == (long long)B_ROWS * N_SPARSE)  sparse_idx = (const int*)d_in[i];
    }

    float* out = (float*)d_out;

    static bool attr_set = false;
    if (!attr_set) {
        cudaFuncSetAttribute(wide_kernel,
                             cudaFuncAttributeMaxDynamicSharedMemorySize, SMEM_TOTAL);
        attr_set = true;
    }

    wide_kernel<<<NBLOCKS, THREADS, SMEM_TOTAL>>>(dense, emb_table,
                                                  cross_table0, cross_table1,
                                                  dense_w, sparse_idx, out);
}